// round 7
// baseline (speedup 1.0000x reference)
#include <cuda_runtime.h>
#include <stdint.h>
#include <math.h>

#define FXc 86.6f
#define NEAR_ 2.0f
#define FAR_ 6.0f
#define DINF 1e10f
#define NSAMP 64
#define NBLOCKS 5000

// ---------------- global scratch ----------------
__device__ float g_z[64], g_dists[64];
__device__ float g_sig_last[10000];
__device__ float g_sb1[256], g_sb2[256], g_sbd[128];
__device__ __align__(16) signed char g_w1q1[256 * 64],  g_w1q2[256 * 64];
__device__ __align__(16) signed char g_w2q1[256 * 256], g_w2q2[256 * 256];
__device__ __align__(16) signed char g_wdq1[128 * 256], g_wdq2[128 * 256];

// ---------------- smem layout (bytes) ----------------
#define P1_OFF 16384u
#define P2_OFF 26624u
#define X1_OFF 36864u
#define X2_OFF 71680u
#define Y1_OFF 106496u
#define Y2_OFF 141312u
#define BS_OFF 176128u
#define SMEM_BYTES 225280   // BS region = 2 stages x 2 planes x 12288 B -> ends exactly here
// float-indexed misc region (within first 16384 bytes)
#define F_RAY   0
#define F_B1    32
#define F_B2    288
#define F_WSIG  544
#define F_WRGB  800
#define F_EDIR  1184
#define F_DC    1248
#define F_SIG   1504
#define F_RGB   1632
#define F_SAP   2016
#define F_SAX   2144
#define F_SAY   2400
#define F_SB1   2656
#define F_SB2   2912
#define F_SBD   3168

// ---------------- asm helpers ----------------
__device__ __forceinline__ uint32_t smem_u32(const void* p) {
    uint32_t a;
    asm("{ .reg .u64 t; cvta.to.shared.u64 t, %1; cvt.u32.u64 %0, t; }" : "=r"(a) : "l"(p));
    return a;
}
__device__ __forceinline__ uint32_t lds32(uint32_t a) {
    uint32_t v; asm volatile("ld.shared.b32 %0, [%1];" : "=r"(v) : "r"(a)); return v;
}
__device__ __forceinline__ void sts16(uint32_t a, uint32_t v) {
    asm volatile("st.shared.u16 [%0], %1;" :: "r"(a), "h"((unsigned short)v));
}
__device__ __forceinline__ void cpa16(uint32_t d, const void* s) {
    asm volatile("cp.async.ca.shared.global [%0], [%1], 16;" :: "r"(d), "l"(s));
}
#define CP_COMMIT() asm volatile("cp.async.commit_group;" ::: "memory")
#define CP_WAIT1()  asm volatile("cp.async.wait_group 1;" ::: "memory")

__device__ __forceinline__ void mma_s8(int* c, const uint32_t* a, uint32_t b0, uint32_t b1) {
    asm volatile(
        "mma.sync.aligned.m16n8k32.row.col.s32.s8.s8.s32 "
        "{%0,%1,%2,%3}, {%4,%5,%6,%7}, {%8,%9}, {%0,%1,%2,%3};"
        : "+r"(c[0]), "+r"(c[1]), "+r"(c[2]), "+r"(c[3])
        : "r"(a[0]), "r"(a[1]), "r"(a[2]), "r"(a[3]), "r"(b0), "r"(b1));
}
__device__ __forceinline__ float qred(float v) {
    v += __shfl_xor_sync(0xffffffffu, v, 1);
    v += __shfl_xor_sync(0xffffffffu, v, 2);
    return v;
}
__device__ __forceinline__ float qmax(float v) {
    v = fmaxf(v, __shfl_xor_sync(0xffffffffu, v, 1));
    v = fmaxf(v, __shfl_xor_sync(0xffffffffu, v, 2));
    return v;
}
// x ~= s*(256*a1 + a2); pack two values' a1s (and a2s) into low 16 bits
__device__ __forceinline__ void qpair(float v0, float v1, float inv, uint32_t& p1, uint32_t& p2) {
    float q0 = rintf(v0 * inv), q1 = rintf(v1 * inv);
    float h0 = rintf(q0 * (1.f / 256.f)), h1 = rintf(q1 * (1.f / 256.f));
    int l0 = (int)(q0 - 256.f * h0), l1 = (int)(q1 - 256.f * h1);
    l0 = min(l0, 127); l1 = min(l1, 127);
    p1 = ((int)h0 & 255) | (((int)h1 & 255) << 8);
    p2 = (l0 & 255) | ((l1 & 255) << 8);
}

// schedule: 28 items = G1{np,ch}x4, G2{np,ch}x16, G3{ch}x8
__device__ __forceinline__ void fill_item(int t, uint32_t bB, int tid) {
    if (t >= 28) return;
    const signed char *s1, *s2; int kst, rb, ch;
    if (t < 4)       { s1 = g_w1q1; s2 = g_w1q2; kst = 64;  rb = (t >> 1) * 128; ch = t & 1; }
    else if (t < 20) { int u = t - 4;  s1 = g_w2q1; s2 = g_w2q2; kst = 256; rb = (u >> 3) * 128; ch = u & 7; }
    else             { int u = t - 20; s1 = g_wdq1; s2 = g_wdq2; kst = 256; rb = 0; ch = u; }
    int row = tid >> 1, half = tid & 1;
    int off = (rb + row) * kst + ch * 32 + half * 16;
    uint32_t d = bB + (uint32_t)(t & 1) * 24576u + (uint32_t)row * 48u + (uint32_t)half * 16u;
    cpa16(d, s1 + off);
    cpa16(d + 12288u, s2 + off);
}

__device__ __forceinline__ void compute_chunk(uint32_t stage, uint32_t a1p, uint32_t a2p,
                                              uint32_t ast, int kbase, int lane, int r0,
                                              int (*Cm)[4], int (*Cx)[4]) {
    uint32_t ab = (uint32_t)r0 * ast + (uint32_t)(lane & 3) * 4u + (uint32_t)kbase;
    uint32_t a1f[4], a2f[4];
    a1f[0] = lds32(a1p + ab);           a1f[1] = lds32(a1p + ab + 8 * ast);
    a1f[2] = lds32(a1p + ab + 16u);     a1f[3] = lds32(a1p + ab + 8 * ast + 16u);
    a2f[0] = lds32(a2p + ab);           a2f[1] = lds32(a2p + ab + 8 * ast);
    a2f[2] = lds32(a2p + ab + 16u);     a2f[3] = lds32(a2p + ab + 8 * ast + 16u);
    uint32_t bb = stage + (uint32_t)(lane >> 2) * 48u + (uint32_t)(lane & 3) * 4u;
    #pragma unroll
    for (int nt = 0; nt < 16; nt++) {
        uint32_t bo = bb + (uint32_t)nt * 384u;
        uint32_t b10 = lds32(bo),           b11 = lds32(bo + 16u);
        uint32_t b20 = lds32(bo + 12288u),  b21 = lds32(bo + 12304u);
        mma_s8(Cm[nt], a1f, b10, b11);
        mma_s8(Cx[nt], a1f, b20, b21);
        mma_s8(Cx[nt], a2f, b10, b11);
    }
}

__device__ __forceinline__ void flushf(float (*Cf)[4], int (*Cm)[4], int (*Cx)[4],
                                       const float* saK, const float* sbN, int lane, int r0) {
    float s0 = saK[r0], s1 = saK[r0 + 8];
    #pragma unroll
    for (int nt = 0; nt < 16; nt++) {
        int n0 = nt * 8 + 2 * (lane & 3);
        float w0 = sbN[n0], w1 = sbN[n0 + 1];
        Cf[nt][0] += s0 * w0 * fmaf((float)Cm[nt][0], 65536.f, (float)Cx[nt][0] * 256.f);
        Cf[nt][1] += s0 * w1 * fmaf((float)Cm[nt][1], 65536.f, (float)Cx[nt][1] * 256.f);
        Cf[nt][2] += s1 * w0 * fmaf((float)Cm[nt][2], 65536.f, (float)Cx[nt][2] * 256.f);
        Cf[nt][3] += s1 * w1 * fmaf((float)Cm[nt][3], 65536.f, (float)Cx[nt][3] * 256.f);
        Cm[nt][0] = Cm[nt][1] = Cm[nt][2] = Cm[nt][3] = 0;
        Cx[nt][0] = Cx[nt][1] = Cx[nt][2] = Cx[nt][3] = 0;
    }
}

#define ZERO_ACC() do { _Pragma("unroll") for (int z = 0; z < 16; z++) { \
    Cm[z][0]=Cm[z][1]=Cm[z][2]=Cm[z][3]=0; Cx[z][0]=Cx[z][1]=Cx[z][2]=Cx[z][3]=0; \
    Cf[z][0]=Cf[z][1]=Cf[z][2]=Cf[z][3]=0.f; } } while (0)

#define STEP(A1P, A2P, AST_, KB) do { \
    CP_WAIT1(); __syncthreads(); \
    compute_chunk(bB + (uint32_t)(t & 1) * 24576u, (A1P), (A2P), (AST_), (KB), lane, r0, Cm, Cx); \
    __syncthreads(); \
    fill_item(t + 2, bB, tid); CP_COMMIT(); t++; \
} while (0)

// ---------------- aux kernels ----------------
__global__ void precompute_kernel(const float* __restrict__ t_rand) {
    __shared__ float zsh[NSAMP];
    int i = threadIdx.x;
    float t   = (float)i / 63.0f;
    float z0  = NEAR_ * (1.0f - t) + FAR_ * t;
    float tn  = (float)(i + 1) / 63.0f;
    float z0n = NEAR_ * (1.0f - tn) + FAR_ * tn;
    float tp  = (float)(i - 1) / 63.0f;
    float z0p = NEAR_ * (1.0f - tp) + FAR_ * tp;
    float upper = (i < NSAMP - 1) ? 0.5f * (z0 + z0n) : z0;
    float lower = (i > 0) ? 0.5f * (z0p + z0) : z0;
    float z = lower + (upper - lower) * t_rand[i];
    zsh[i] = z;
    g_z[i] = z;
    __syncthreads();
    g_dists[i] = (i < NSAMP - 1) ? (zsh[i + 1] - zsh[i]) : DINF;
}

__global__ void prep_weights(const float* __restrict__ w1,
                             const float* __restrict__ w2,
                             const float* __restrict__ wd) {
    int n = blockIdx.x * 256 + threadIdx.x;
    if (n < 256) {
        float m = 0.f;
        for (int k = 0; k < 63; k++) m = fmaxf(m, fabsf(w1[k * 256 + n] * ((k < 3) ? 8.f : 1.f)));
        float inv = m > 0.f ? 32512.f / m : 0.f;
        g_sb1[n] = m * (1.f / 32512.f);
        for (int k = 0; k < 64; k++) {
            float v = (k < 63) ? w1[k * 256 + n] * ((k < 3) ? 8.f : 1.f) : 0.f;
            uint32_t p1, p2; qpair(v, 0.f, inv, p1, p2);
            g_w1q1[n * 64 + k] = (signed char)(p1 & 255);
            g_w1q2[n * 64 + k] = (signed char)(p2 & 255);
        }
    } else if (n < 512) {
        int c = n - 256;
        float m = 0.f;
        for (int k = 0; k < 256; k++) m = fmaxf(m, fabsf(w2[k * 256 + c]));
        float inv = m > 0.f ? 32512.f / m : 0.f;
        g_sb2[c] = m * (1.f / 32512.f);
        for (int k = 0; k < 256; k++) {
            uint32_t p1, p2; qpair(w2[k * 256 + c], 0.f, inv, p1, p2);
            g_w2q1[c * 256 + k] = (signed char)(p1 & 255);
            g_w2q2[c * 256 + k] = (signed char)(p2 & 255);
        }
    } else if (n < 640) {
        int c = n - 512;
        float m = 0.f;
        for (int k = 0; k < 256; k++) m = fmaxf(m, fabsf(wd[k * 128 + c]));
        float inv = m > 0.f ? 32512.f / m : 0.f;
        g_sbd[c] = m * (1.f / 32512.f);
        for (int k = 0; k < 256; k++) {
            uint32_t p1, p2; qpair(wd[k * 128 + c], 0.f, inv, p1, p2);
            g_wdq1[c * 256 + k] = (signed char)(p1 & 255);
            g_wdq2[c * 256 + k] = (signed char)(p2 & 255);
        }
    }
}

// exact fp32 sigma for the LAST sample of each ray (alpha there is a step fn of sign(sigma))
__global__ void __launch_bounds__(256) sigma_exact(
    const float* __restrict__ c2w,
    const float* __restrict__ w1g, const float* __restrict__ b1g,
    const float* __restrict__ w2g, const float* __restrict__ b2g,
    const float* __restrict__ wsigg, const float* __restrict__ bsigg)
{
    __shared__ float enc[16][64];
    __shared__ float h1s[16][260];
    __shared__ float red[16][8];
    int tid = threadIdx.x;
    int r = tid >> 4, sub = tid & 15;
    {
        int ray = blockIdx.x * 16 + r;
        int cx = ray % 100, rw = ray / 100;
        float dx = ((float)cx - 50.0f) / FXc;
        float dy = -(((float)rw - 50.0f) / FXc);
        float d0 = dx * c2w[0] + dy * c2w[1] - c2w[2];
        float d1 = dx * c2w[4] + dy * c2w[5] - c2w[6];
        float d2 = dx * c2w[8] + dy * c2w[9] - c2w[10];
        float z = g_z[63];
        float pt[3];
        pt[0] = fmaf(d0, z, c2w[3]);
        pt[1] = fmaf(d1, z, c2w[7]);
        pt[2] = fmaf(d2, z, c2w[11]);
        #pragma unroll
        for (int q = 0; q < 4; q++) {
            int dd = sub * 4 + q;
            float val = 0.f;
            if (dd < 3) val = pt[dd];
            else if (dd < 63) {
                int u = dd - 3, l = u / 6, r6 = u % 6, cc = r6 % 3;
                float x = pt[cc] * (float)(1 << l);
                val = (r6 < 3) ? sinf(x) : cosf(x);
            }
            enc[r][dd] = val;
        }
    }
    __syncthreads();
    float acc[16];
    {
        float b = b1g[tid];
        #pragma unroll
        for (int i = 0; i < 16; i++) acc[i] = b;
        #pragma unroll 1
        for (int k = 0; k < 63; k++) {
            float w = w1g[k * 256 + tid];
            #pragma unroll
            for (int i = 0; i < 16; i++) acc[i] = fmaf(enc[i][k], w, acc[i]);
        }
        #pragma unroll
        for (int i = 0; i < 16; i++) h1s[i][tid] = fmaxf(acc[i], 0.f);
    }
    __syncthreads();
    {
        float b = b2g[tid];
        #pragma unroll
        for (int i = 0; i < 16; i++) acc[i] = b;
        #pragma unroll 1
        for (int k = 0; k < 256; k++) {
            float w = w2g[k * 256 + tid];
            #pragma unroll
            for (int i = 0; i < 16; i++) acc[i] = fmaf(h1s[i][k], w, acc[i]);
        }
    }
    {
        float ws = wsigg[tid];
        #pragma unroll
        for (int i = 0; i < 16; i++) {
            float v = fmaxf(acc[i], 0.f) * ws;
            v += __shfl_xor_sync(0xffffffffu, v, 16);
            v += __shfl_xor_sync(0xffffffffu, v, 8);
            v += __shfl_xor_sync(0xffffffffu, v, 4);
            v += __shfl_xor_sync(0xffffffffu, v, 2);
            v += __shfl_xor_sync(0xffffffffu, v, 1);
            if ((tid & 31) == 0) red[i][tid >> 5] = v;
        }
        __syncthreads();
        if (tid < 16) {
            float s = bsigg[0];
            #pragma unroll
            for (int w = 0; w < 8; w++) s += red[tid][w];
            g_sig_last[blockIdx.x * 16 + tid] = s;
        }
    }
}

// ---------------- main fused kernel ----------------
__global__ void __launch_bounds__(256, 1) nerf_imma(
    const float* __restrict__ c2w,
    const float* __restrict__ b1g,  const float* __restrict__ b2g,
    const float* __restrict__ wsigg,const float* __restrict__ bsigg,
    const float* __restrict__ wdirg,const float* __restrict__ bdirg,
    const float* __restrict__ wrgbg,const float* __restrict__ brgbg,
    float* __restrict__ out)
{
    extern __shared__ char smraw[];
    float* smf = (float*)smraw;
    const uint32_t base = smem_u32(smraw);
    const uint32_t bB = base + BS_OFF;
    const uint32_t P1u = base + P1_OFF, P2u = base + P2_OFF;
    const uint32_t X1u = base + X1_OFF, X2u = base + X2_OFF;
    const uint32_t Y1u = base + Y1_OFF, Y2u = base + Y2_OFF;
    const int tid = threadIdx.x, lane = tid & 31, wid = tid >> 5;
    const int r0 = 16 * wid + (lane >> 2);
    const int ray0 = blockIdx.x * 2;

    fill_item(0, bB, tid); CP_COMMIT();
    fill_item(1, bB, tid); CP_COMMIT();

    {
        int i = tid;
        smf[F_B1 + i] = b1g[i]; smf[F_B2 + i] = b2g[i]; smf[F_WSIG + i] = wsigg[i];
        smf[F_SB1 + i] = g_sb1[i]; smf[F_SB2 + i] = g_sb2[i];
        if (i < 128) smf[F_SBD + i] = g_sbd[i];
        for (int j = i; j < 384; j += 256) smf[F_WRGB + j] = wrgbg[j];
    }
    if (tid < 2) {
        int ray = ray0 + tid;
        int c = ray % 100, rw = ray / 100;
        float dx = ((float)c - 50.0f) / FXc;
        float dy = -(((float)rw - 50.0f) / FXc);
        float d0 = dx * c2w[0] + dy * c2w[1] - c2w[2];
        float d1 = dx * c2w[4] + dy * c2w[5] - c2w[6];
        float d2 = dx * c2w[8] + dy * c2w[9] - c2w[10];
        float nrm = sqrtf(d0 * d0 + d1 * d1 + d2 * d2);
        float* R = smf + F_RAY + tid * 12;
        R[0] = c2w[3]; R[1] = c2w[7]; R[2] = c2w[11];
        R[3] = d0; R[4] = d1; R[5] = d2;
        R[6] = d0 / nrm; R[7] = d1 / nrm; R[8] = d2 / nrm;
        R[9] = nrm;
    }
    __syncthreads();

    if (tid < 54) {
        int rr = tid / 27, dd = tid - rr * 27;
        const float* vv = smf + F_RAY + rr * 12 + 6;
        float val;
        if (dd < 3) val = vv[dd];
        else {
            int u = dd - 3, l = u / 6, r6 = u % 6, cc = r6 % 3;
            float x = vv[cc] * (float)(1 << l);
            val = (r6 < 3) ? sinf(x) : cosf(x);
        }
        smf[F_EDIR + rr * 32 + dd] = val;
    }
    __syncthreads();

    // dir-head rank-1 bias dc[2][128] (fp32)
    {
        int j = tid & 127, rr = tid >> 7;
        float acc = bdirg[j];
        #pragma unroll
        for (int dd = 0; dd < 27; dd++)
            acc = fmaf(smf[F_EDIR + rr * 32 + dd], wdirg[(256 + dd) * 128 + j], acc);
        smf[F_DC + rr * 128 + j] = acc;
    }

    // posenc + quantize -> P planes (xyz prescaled 1/8; x8 folded into w1 cols)
    if (tid < 128) {
        int rr = tid >> 6, s = tid & 63;
        float z = g_z[s];
        const float* R = smf + F_RAY + rr * 12;
        float v[64];
        float f0 = fmaf(R[3], z, R[0]);
        float f1 = fmaf(R[4], z, R[1]);
        float f2 = fmaf(R[5], z, R[2]);
        v[0] = f0 * 0.125f; v[1] = f1 * 0.125f; v[2] = f2 * 0.125f;
        #pragma unroll
        for (int l = 0; l < 10; l++) {
            float s0, c0, s1, c1, s2, c2;
            sincosf(f0, &s0, &c0); sincosf(f1, &s1, &c1); sincosf(f2, &s2, &c2);
            int b = 3 + l * 6;
            v[b] = s0; v[b + 1] = s1; v[b + 2] = s2;
            v[b + 3] = c0; v[b + 4] = c1; v[b + 5] = c2;
            f0 *= 2.0f; f1 *= 2.0f; f2 *= 2.0f;
        }
        v[63] = 0.0f;
        float m = 0.f;
        #pragma unroll
        for (int i = 0; i < 63; i++) m = fmaxf(m, fabsf(v[i]));
        float inv = 32512.f / m;
        smf[F_SAP + tid] = m * (1.f / 32512.f);
        uint32_t w1r[16], w2r[16];
        #pragma unroll
        for (int i = 0; i < 16; i++) {
            uint32_t a1, a2, b1, b2;
            qpair(v[4 * i], v[4 * i + 1], inv, a1, a2);
            qpair(v[4 * i + 2], v[4 * i + 3], inv, b1, b2);
            w1r[i] = (a1 & 0xFFFF) | (b1 << 16);
            w2r[i] = (a2 & 0xFFFF) | (b2 << 16);
        }
        char* p1 = smraw + P1_OFF + tid * 80;
        char* p2 = smraw + P2_OFF + tid * 80;
        #pragma unroll
        for (int q = 0; q < 4; q++) {
            *(uint4*)(p1 + 16 * q) = ((uint4*)w1r)[q];
            *(uint4*)(p2 + 16 * q) = ((uint4*)w2r)[q];
        }
    }

    int t = 0;
    int Cm[16][4], Cx[16][4];
    float Cf[16][4];

    // ============ GEMM1: h1 = relu(enc @ w1 + b1), N=256 in 2 passes, K=64 ============
    #pragma unroll 1
    for (int np = 0; np < 2; np++) {
        ZERO_ACC();
        STEP(P1u, P2u, 80u, 0);
        STEP(P1u, P2u, 80u, 32);
        flushf(Cf, Cm, Cx, smf + F_SAP, smf + F_SB1 + np * 128, lane, r0);
        // epilogue -> X planes + F_SAX scales
        float m0 = 0.f, m1 = 0.f;
        #pragma unroll
        for (int nt = 0; nt < 16; nt++) {
            int cg = np * 128 + nt * 8 + 2 * (lane & 3);
            float b0v = smf[F_B1 + cg], b1v = smf[F_B1 + cg + 1];
            Cf[nt][0] = fmaxf(Cf[nt][0] + b0v, 0.f);
            Cf[nt][1] = fmaxf(Cf[nt][1] + b1v, 0.f);
            Cf[nt][2] = fmaxf(Cf[nt][2] + b0v, 0.f);
            Cf[nt][3] = fmaxf(Cf[nt][3] + b1v, 0.f);
            m0 = fmaxf(m0, fmaxf(Cf[nt][0], Cf[nt][1]));
            m1 = fmaxf(m1, fmaxf(Cf[nt][2], Cf[nt][3]));
        }
        m0 = qmax(m0); m1 = qmax(m1);
        float inv0 = m0 > 0.f ? 32512.f / m0 : 0.f;
        float inv1 = m1 > 0.f ? 32512.f / m1 : 0.f;
        if ((lane & 3) == 0) {
            smf[F_SAX + np * 128 + r0]     = m0 * (1.f / 32512.f);
            smf[F_SAX + np * 128 + r0 + 8] = m1 * (1.f / 32512.f);
        }
        #pragma unroll
        for (int nt = 0; nt < 16; nt++) {
            uint32_t o = (uint32_t)r0 * 272u + (uint32_t)(np * 128 + nt * 8 + 2 * (lane & 3));
            uint32_t p1, p2;
            qpair(Cf[nt][0], Cf[nt][1], inv0, p1, p2);
            sts16(X1u + o, p1); sts16(X2u + o, p2);
            qpair(Cf[nt][2], Cf[nt][3], inv1, p1, p2);
            sts16(X1u + o + 8 * 272u, p1); sts16(X2u + o + 8 * 272u, p2);
        }
    }

    // ============ GEMM2: h2 = relu(h1 @ w2 + b2), N=256 in 2 passes, K=256 ============
    float sl = 0.f, sh = 0.f;
    #pragma unroll 1
    for (int np = 0; np < 2; np++) {
        ZERO_ACC();
        #pragma unroll 1
        for (int ch = 0; ch < 8; ch++) {
            STEP(X1u, X2u, 272u, ch * 32);
            if (ch == 3) flushf(Cf, Cm, Cx, smf + F_SAX, smf + F_SB2 + np * 128, lane, r0);
        }
        flushf(Cf, Cm, Cx, smf + F_SAX + 128, smf + F_SB2 + np * 128, lane, r0);
        float m0 = 0.f, m1 = 0.f;
        #pragma unroll
        for (int nt = 0; nt < 16; nt++) {
            int cg = np * 128 + nt * 8 + 2 * (lane & 3);
            float b0v = smf[F_B2 + cg], b1v = smf[F_B2 + cg + 1];
            float w0 = smf[F_WSIG + cg], w1v = smf[F_WSIG + cg + 1];
            Cf[nt][0] = fmaxf(Cf[nt][0] + b0v, 0.f);
            Cf[nt][1] = fmaxf(Cf[nt][1] + b1v, 0.f);
            Cf[nt][2] = fmaxf(Cf[nt][2] + b0v, 0.f);
            Cf[nt][3] = fmaxf(Cf[nt][3] + b1v, 0.f);
            sl = fmaf(Cf[nt][0], w0, fmaf(Cf[nt][1], w1v, sl));
            sh = fmaf(Cf[nt][2], w0, fmaf(Cf[nt][3], w1v, sh));
            m0 = fmaxf(m0, fmaxf(Cf[nt][0], Cf[nt][1]));
            m1 = fmaxf(m1, fmaxf(Cf[nt][2], Cf[nt][3]));
        }
        m0 = qmax(m0); m1 = qmax(m1);
        float inv0 = m0 > 0.f ? 32512.f / m0 : 0.f;
        float inv1 = m1 > 0.f ? 32512.f / m1 : 0.f;
        if ((lane & 3) == 0) {
            smf[F_SAY + np * 128 + r0]     = m0 * (1.f / 32512.f);
            smf[F_SAY + np * 128 + r0 + 8] = m1 * (1.f / 32512.f);
        }
        #pragma unroll
        for (int nt = 0; nt < 16; nt++) {
            uint32_t o = (uint32_t)r0 * 272u + (uint32_t)(np * 128 + nt * 8 + 2 * (lane & 3));
            uint32_t p1, p2;
            qpair(Cf[nt][0], Cf[nt][1], inv0, p1, p2);
            sts16(Y1u + o, p1); sts16(Y2u + o, p2);
            qpair(Cf[nt][2], Cf[nt][3], inv1, p1, p2);
            sts16(Y1u + o + 8 * 272u, p1); sts16(Y2u + o + 8 * 272u, p2);
        }
    }
    sl = qred(sl); sh = qred(sh);
    if ((lane & 3) == 0) {
        float bs0 = bsigg[0];
        smf[F_SIG + r0]     = sl + bs0;
        smf[F_SIG + r0 + 8] = sh + bs0;
    }

    // ============ GEMM3: hd = relu(h2 @ w_dir_top + dc), N=128 (1 pass), K=256 ========
    ZERO_ACC();
    #pragma unroll 1
    for (int ch = 0; ch < 8; ch++) {
        STEP(Y1u, Y2u, 272u, ch * 32);
        if (ch == 3) flushf(Cf, Cm, Cx, smf + F_SAY, smf + F_SBD, lane, r0);
    }
    flushf(Cf, Cm, Cx, smf + F_SAY + 128, smf + F_SBD, lane, r0);
    {   // fused rgb head
        int ray = r0 >> 6;
        const float* dcp = smf + F_DC + ray * 128;
        float rr0 = 0.f, gg0 = 0.f, bb0 = 0.f, rr1 = 0.f, gg1 = 0.f, bb1 = 0.f;
        #pragma unroll
        for (int nt = 0; nt < 16; nt++) {
            int col = nt * 8 + 2 * (lane & 3);
            float d0 = dcp[col], d1 = dcp[col + 1];
            float h0 = fmaxf(Cf[nt][0] + d0, 0.f), h1 = fmaxf(Cf[nt][1] + d1, 0.f);
            float h2 = fmaxf(Cf[nt][2] + d0, 0.f), h3 = fmaxf(Cf[nt][3] + d1, 0.f);
            const float* w0 = smf + F_WRGB + col * 3;
            const float* w1v = w0 + 3;
            rr0 = fmaf(h0, w0[0], fmaf(h1, w1v[0], rr0));
            gg0 = fmaf(h0, w0[1], fmaf(h1, w1v[1], gg0));
            bb0 = fmaf(h0, w0[2], fmaf(h1, w1v[2], bb0));
            rr1 = fmaf(h2, w0[0], fmaf(h3, w1v[0], rr1));
            gg1 = fmaf(h2, w0[1], fmaf(h3, w1v[1], gg1));
            bb1 = fmaf(h2, w0[2], fmaf(h3, w1v[2], bb1));
        }
        rr0 = qred(rr0); gg0 = qred(gg0); bb0 = qred(bb0);
        rr1 = qred(rr1); gg1 = qred(gg1); bb1 = qred(bb1);
        if ((lane & 3) == 0) {
            float br = brgbg[0], bg = brgbg[1], bbv = brgbg[2];
            smf[F_RGB + r0 * 3 + 0] = 1.0f / (1.0f + expf(-(rr0 + br)));
            smf[F_RGB + r0 * 3 + 1] = 1.0f / (1.0f + expf(-(gg0 + bg)));
            smf[F_RGB + r0 * 3 + 2] = 1.0f / (1.0f + expf(-(bb0 + bbv)));
            smf[F_RGB + (r0 + 8) * 3 + 0] = 1.0f / (1.0f + expf(-(rr1 + br)));
            smf[F_RGB + (r0 + 8) * 3 + 1] = 1.0f / (1.0f + expf(-(gg1 + bg)));
            smf[F_RGB + (r0 + 8) * 3 + 2] = 1.0f / (1.0f + expf(-(bb1 + bbv)));
        }
    }
    __syncthreads();

    if (tid < 2) {
        int ray = ray0 + tid;
        float nrm = smf[F_RAY + tid * 12 + 9];
        float sig_last = g_sig_last[ray];   // exact fp32 sigma for the step-function sample
        float T = 1.0f, r = 0.0f, g = 0.0f, b = 0.0f;
        #pragma unroll 1
        for (int s = 0; s < NSAMP; s++) {
            int m = tid * 64 + s;
            float sg = (s == 63) ? sig_last : smf[F_SIG + m];
            sg = fmaxf(sg, 0.0f);
            float a = 1.0f - expf(-sg * g_dists[s] * nrm);
            float w = a * T;
            r = fmaf(w, smf[F_RGB + m * 3 + 0], r);
            g = fmaf(w, smf[F_RGB + m * 3 + 1], g);
            b = fmaf(w, smf[F_RGB + m * 3 + 2], b);
            T *= (1.0f - a);
        }
        out[ray * 3 + 0] = r;
        out[ray * 3 + 1] = g;
        out[ray * 3 + 2] = b;
    }
}

extern "C" void kernel_launch(void* const* d_in, const int* in_sizes, int n_in,
                              void* d_out, int out_size) {
    const float* c2w    = (const float*)d_in[0];
    const float* t_rand = (const float*)d_in[1];
    const float* w1     = (const float*)d_in[2];
    const float* b1     = (const float*)d_in[3];
    const float* w2     = (const float*)d_in[4];
    const float* b2     = (const float*)d_in[5];
    const float* w_sig  = (const float*)d_in[6];
    const float* b_sig  = (const float*)d_in[7];
    const float* w_dir  = (const float*)d_in[8];
    const float* b_dir  = (const float*)d_in[9];
    const float* w_rgb  = (const float*)d_in[10];
    const float* b_rgb  = (const float*)d_in[11];
    float* out = (float*)d_out;

    cudaFuncSetAttribute(nerf_imma, cudaFuncAttributeMaxDynamicSharedMemorySize, SMEM_BYTES);

    precompute_kernel<<<1, NSAMP>>>(t_rand);
    prep_weights<<<3, 256>>>(w1, w2, w_dir);
    sigma_exact<<<625, 256>>>(c2w, w1, b1, w2, b2, w_sig, b_sig);
    nerf_imma<<<NBLOCKS, 256, SMEM_BYTES>>>(c2w, b1, b2, w_sig, b_sig,
                                            w_dir, b_dir, w_rgb, b_rgb, out);
}

// round 8
// speedup vs baseline: 4.2375x; 4.2375x over previous
#include <cuda_runtime.h>
#include <cuda_fp16.h>
#include <stdint.h>
#include <math.h>

#define NSAMP 64
#define NBLOCKS 5000           // 2 rays per block, M = 128 sample-rows
#define FXc 86.6f
#define NEAR_ 2.0f
#define FAR_ 6.0f
#define DINF 1e10f

// ---------------- global scratch (weights as fp16, [N][K]) ----------------
__device__ float g_z[NSAMP];
__device__ float g_dists[NSAMP];
__device__ float g_sig_last[10000];
__device__ __align__(16) __half g_w1T[256 * 64];
__device__ __align__(16) __half g_w2T[256 * 256];
__device__ __align__(16) __half g_wdT[128 * 256];

// ---------------- smem layout (bytes) ----------------
// [0, 8192)        misc floats
// [8192, 75776)    A plane: 128 rows x 264 fp16 (row stride 528 B)
// [75776, 116736)  B stages: 2 x 20480 B (256 rows x 40 fp16)
#define A_OFF     8192u
#define B_OFF     75776u
#define STAGE_B   20480u
#define AROW      528u
#define SMEM_BYTES 116736

// misc float offsets
#define F_RAY   0      // [2][12]: o(3) d(3) v(3) norm
#define F_B1    32
#define F_B2    288
#define F_WSIG  544
#define F_WRGB  800    // 384
#define F_EDIR  1184   // [2][32]
#define F_DC    1248   // [2][128]
#define F_SIG   1504   // [128]
#define F_RGB   1632   // [128][3]

// ---------------- asm helpers ----------------
__device__ __forceinline__ uint32_t smem_u32(const void* p) {
    uint32_t a;
    asm("{ .reg .u64 t; cvta.to.shared.u64 t, %1; cvt.u32.u64 %0, t; }" : "=r"(a) : "l"(p));
    return a;
}
__device__ __forceinline__ uint32_t lds32(uint32_t a) {
    uint32_t v; asm volatile("ld.shared.b32 %0, [%1];" : "=r"(v) : "r"(a)); return v;
}
__device__ __forceinline__ void sts32(uint32_t a, uint32_t v) {
    asm volatile("st.shared.b32 [%0], %1;" :: "r"(a), "r"(v));
}
__device__ __forceinline__ void mma_f16(float* c, const uint32_t* a, uint32_t b0, uint32_t b1) {
    asm volatile(
        "mma.sync.aligned.m16n8k16.row.col.f32.f16.f16.f32 "
        "{%0,%1,%2,%3}, {%4,%5,%6,%7}, {%8,%9}, {%0,%1,%2,%3};"
        : "+f"(c[0]), "+f"(c[1]), "+f"(c[2]), "+f"(c[3])
        : "r"(a[0]), "r"(a[1]), "r"(a[2]), "r"(a[3]), "r"(b0), "r"(b1));
}
__device__ __forceinline__ void cpa16(uint32_t d, const void* s) {
    asm volatile("cp.async.ca.shared.global [%0], [%1], 16;" :: "r"(d), "l"(s));
}
#define CP_COMMIT() asm volatile("cp.async.commit_group;" ::: "memory")
#define CP_WAIT1()  asm volatile("cp.async.wait_group 1;" ::: "memory")

__device__ __forceinline__ uint32_t pack_h2(float a, float b) {
    __half2 h = __floats2half2_rn(a, b);
    return *reinterpret_cast<uint32_t*>(&h);
}
__device__ __forceinline__ float qred(float v) {
    v += __shfl_xor_sync(0xffffffffu, v, 1);
    v += __shfl_xor_sync(0xffffffffu, v, 2);
    return v;
}

// fill one K=32 chunk: rows [0,nrows) of [N][K] fp16 -> stage (rows padded to 40 fp16)
__device__ __forceinline__ void cp_fill(uint32_t dst, const __half* __restrict__ src,
                                        int nrows, int kstride, int kbase, int tid) {
    int total = nrows * 4;
    for (int i = tid; i < total; i += 256) {
        int n = i >> 2, seg = i & 3;
        cpa16(dst + (uint32_t)n * 80u + (uint32_t)seg * 16u,
              (const char*)(src + n * kstride + kbase) + seg * 16);
    }
}

// GEMM over M=128 (8 warps x 16 rows), N = NT*8, K = nchunks*32, single fp16 product.
template<int NT>
__device__ __forceinline__ void gemm_run(float (*C)[4], int nchunks, int nrows_b,
                                         const __half* __restrict__ src, int kstride,
                                         uint32_t aP, uint32_t bBase, int tid) {
    const int lane = tid & 31, wid = tid >> 5;
    const uint32_t arow = (uint32_t)(16 * wid + (lane >> 2)) * AROW + (uint32_t)(lane & 3) * 4u;
    const uint32_t brow = (uint32_t)(lane >> 2) * 80u + (uint32_t)(lane & 3) * 4u;
    #pragma unroll
    for (int t = 0; t < NT; t++) { C[t][0] = 0.f; C[t][1] = 0.f; C[t][2] = 0.f; C[t][3] = 0.f; }
    #pragma unroll 1
    for (int ch = 0; ch < nchunks; ch++) {
        CP_WAIT1();
        __syncthreads();
        uint32_t bs = bBase + (uint32_t)(ch & 1) * STAGE_B;
        #pragma unroll
        for (int k16 = 0; k16 < 2; k16++) {
            uint32_t kb = (uint32_t)(ch * 32 + k16 * 16) * 2u;
            uint32_t ah = aP + arow + kb;
            uint32_t a[4];
            a[0] = lds32(ah);          a[1] = lds32(ah + 8 * AROW);
            a[2] = lds32(ah + 16);     a[3] = lds32(ah + 8 * AROW + 16);
            uint32_t bk = bs + brow + (uint32_t)k16 * 32u;
            #pragma unroll
            for (int nt = 0; nt < NT; nt++) {
                uint32_t ba = bk + (uint32_t)nt * 640u;
                mma_f16(C[nt], a, lds32(ba), lds32(ba + 16));
            }
        }
        __syncthreads();
        if (ch + 2 < nchunks)
            cp_fill(bBase + (uint32_t)(ch & 1) * STAGE_B, src, nrows_b, kstride,
                    (ch + 2) * 32, tid);
        CP_COMMIT();
    }
}

// ---------------- aux kernels ----------------
__global__ void precompute_kernel(const float* __restrict__ t_rand) {
    __shared__ float zsh[NSAMP];
    int i = threadIdx.x;
    float t   = (float)i / 63.0f;
    float z0  = NEAR_ * (1.0f - t) + FAR_ * t;
    float tn  = (float)(i + 1) / 63.0f;
    float z0n = NEAR_ * (1.0f - tn) + FAR_ * tn;
    float tp  = (float)(i - 1) / 63.0f;
    float z0p = NEAR_ * (1.0f - tp) + FAR_ * tp;
    float upper = (i < NSAMP - 1) ? 0.5f * (z0 + z0n) : z0;
    float lower = (i > 0) ? 0.5f * (z0p + z0) : z0;
    float z = lower + (upper - lower) * t_rand[i];
    zsh[i] = z;
    g_z[i] = z;
    __syncthreads();
    g_dists[i] = (i < NSAMP - 1) ? (zsh[i + 1] - zsh[i]) : DINF;
}

__global__ void prep_weights(const float* __restrict__ w1,
                             const float* __restrict__ w2,
                             const float* __restrict__ wd) {
    int idx = blockIdx.x * 256 + threadIdx.x;
    if (idx < 16384) {
        int n = idx >> 6, k = idx & 63;
        g_w1T[idx] = __float2half((k < 63) ? w1[k * 256 + n] : 0.0f);
    } else if (idx < 16384 + 65536) {
        int t = idx - 16384; int n = t >> 8, k = t & 255;
        g_w2T[t] = __float2half(w2[k * 256 + n]);
    } else if (idx < 16384 + 65536 + 32768) {
        int t = idx - 16384 - 65536; int n = t >> 8, k = t & 255;
        g_wdT[t] = __float2half(wd[k * 128 + n]);
    }
}

// exact fp32 sigma for the LAST sample of each ray (alpha there is a step fn of sign(sigma))
__global__ void __launch_bounds__(256) sigma_exact(
    const float* __restrict__ c2w,
    const float* __restrict__ w1g, const float* __restrict__ b1g,
    const float* __restrict__ w2g, const float* __restrict__ b2g,
    const float* __restrict__ wsigg, const float* __restrict__ bsigg)
{
    __shared__ float enc[16][64];
    __shared__ float h1s[16][260];
    __shared__ float red[16][8];
    int tid = threadIdx.x;
    int r = tid >> 4, sub = tid & 15;
    {
        int ray = blockIdx.x * 16 + r;
        int cx = ray % 100, rw = ray / 100;
        float dx = ((float)cx - 50.0f) / FXc;
        float dy = -(((float)rw - 50.0f) / FXc);
        float d0 = dx * c2w[0] + dy * c2w[1] - c2w[2];
        float d1 = dx * c2w[4] + dy * c2w[5] - c2w[6];
        float d2 = dx * c2w[8] + dy * c2w[9] - c2w[10];
        float z = g_z[63];
        float pt[3];
        pt[0] = fmaf(d0, z, c2w[3]);
        pt[1] = fmaf(d1, z, c2w[7]);
        pt[2] = fmaf(d2, z, c2w[11]);
        #pragma unroll
        for (int q = 0; q < 4; q++) {
            int dd = sub * 4 + q;
            float val = 0.f;
            if (dd < 3) val = pt[dd];
            else if (dd < 63) {
                int u = dd - 3, l = u / 6, r6 = u % 6, cc = r6 % 3;
                float x = pt[cc] * (float)(1 << l);
                val = (r6 < 3) ? sinf(x) : cosf(x);
            }
            enc[r][dd] = val;
        }
    }
    __syncthreads();
    float acc[16];
    {
        float b = b1g[tid];
        #pragma unroll
        for (int i = 0; i < 16; i++) acc[i] = b;
        #pragma unroll 1
        for (int k = 0; k < 63; k++) {
            float w = w1g[k * 256 + tid];
            #pragma unroll
            for (int i = 0; i < 16; i++) acc[i] = fmaf(enc[i][k], w, acc[i]);
        }
        #pragma unroll
        for (int i = 0; i < 16; i++) h1s[i][tid] = fmaxf(acc[i], 0.f);
    }
    __syncthreads();
    {
        float b = b2g[tid];
        #pragma unroll
        for (int i = 0; i < 16; i++) acc[i] = b;
        #pragma unroll 1
        for (int k = 0; k < 256; k++) {
            float w = w2g[k * 256 + tid];
            #pragma unroll
            for (int i = 0; i < 16; i++) acc[i] = fmaf(h1s[i][k], w, acc[i]);
        }
    }
    {
        float ws = wsigg[tid];
        #pragma unroll
        for (int i = 0; i < 16; i++) {
            float v = fmaxf(acc[i], 0.f) * ws;
            v += __shfl_xor_sync(0xffffffffu, v, 16);
            v += __shfl_xor_sync(0xffffffffu, v, 8);
            v += __shfl_xor_sync(0xffffffffu, v, 4);
            v += __shfl_xor_sync(0xffffffffu, v, 2);
            v += __shfl_xor_sync(0xffffffffu, v, 1);
            if ((tid & 31) == 0) red[i][tid >> 5] = v;
        }
        __syncthreads();
        if (tid < 16) {
            float s = bsigg[0];
            #pragma unroll
            for (int w = 0; w < 8; w++) s += red[tid][w];
            g_sig_last[blockIdx.x * 16 + tid] = s;
        }
    }
}

// ---------------- main fused kernel ----------------
__global__ void __launch_bounds__(256, 1) nerf_hmma16(
    const float* __restrict__ c2w,
    const float* __restrict__ b1g,  const float* __restrict__ b2g,
    const float* __restrict__ wsigg,const float* __restrict__ bsigg,
    const float* __restrict__ wdirg,const float* __restrict__ bdirg,
    const float* __restrict__ wrgbg,const float* __restrict__ brgbg,
    float* __restrict__ out)
{
    extern __shared__ char smraw[];
    float* smf = (float*)smraw;
    const uint32_t base = smem_u32(smraw);
    const uint32_t aP = base + A_OFF, bB = base + B_OFF;
    const int tid = threadIdx.x, lane = tid & 31, wid = tid >> 5;
    const int ray0 = blockIdx.x * 2;

    // prefetch GEMM1's two K-chunks of w1T (2 groups)
    cp_fill(bB,           g_w1T, 256, 64, 0,  tid); CP_COMMIT();
    cp_fill(bB + STAGE_B, g_w1T, 256, 64, 32, tid); CP_COMMIT();

    // stage small tensors
    for (int i = tid; i < 256; i += 256) {
        smf[F_B1 + i]   = b1g[i];
        smf[F_B2 + i]   = b2g[i];
        smf[F_WSIG + i] = wsigg[i];
    }
    for (int i = tid; i < 384; i += 256) smf[F_WRGB + i] = wrgbg[i];
    if (tid < 2) {
        int ray = ray0 + tid;
        int c = ray % 100, rw = ray / 100;
        float dx = ((float)c - 50.0f) / FXc;
        float dy = -(((float)rw - 50.0f) / FXc);
        float d0 = dx * c2w[0] + dy * c2w[1] - c2w[2];
        float d1 = dx * c2w[4] + dy * c2w[5] - c2w[6];
        float d2 = dx * c2w[8] + dy * c2w[9] - c2w[10];
        float nrm = sqrtf(d0 * d0 + d1 * d1 + d2 * d2);
        float* R = smf + F_RAY + tid * 12;
        R[0] = c2w[3]; R[1] = c2w[7]; R[2] = c2w[11];
        R[3] = d0; R[4] = d1; R[5] = d2;
        R[6] = d0 / nrm; R[7] = d1 / nrm; R[8] = d2 / nrm;
        R[9] = nrm;
    }
    __syncthreads();

    // enc_dir (27 per ray)
    if (tid < 54) {
        int rr = tid / 27, dd = tid - rr * 27;
        const float* vv = smf + F_RAY + rr * 12 + 6;
        float val;
        if (dd < 3) val = vv[dd];
        else {
            int u = dd - 3, l = u / 6, r6 = u % 6, cc = r6 % 3;
            float x = vv[cc] * (float)(1 << l);
            val = (r6 < 3) ? sinf(x) : cosf(x);
        }
        smf[F_EDIR + rr * 32 + dd] = val;
    }

    // posenc(pts): 128 rows x 63 dims -> A plane fp16 (cols 0..63, col 63 zero)
    if (tid < 128) {
        int rr = tid >> 6, s = tid & 63;
        float z = g_z[s];
        const float* R = smf + F_RAY + rr * 12;
        float v[64];
        float f0 = fmaf(R[3], z, R[0]);
        float f1 = fmaf(R[4], z, R[1]);
        float f2 = fmaf(R[5], z, R[2]);
        v[0] = f0; v[1] = f1; v[2] = f2;
        #pragma unroll
        for (int l = 0; l < 10; l++) {
            float s0, c0, s1, c1, s2, c2;
            sincosf(f0, &s0, &c0); sincosf(f1, &s1, &c1); sincosf(f2, &s2, &c2);
            int b = 3 + l * 6;
            v[b] = s0; v[b + 1] = s1; v[b + 2] = s2;
            v[b + 3] = c0; v[b + 4] = c1; v[b + 5] = c2;
            f0 *= 2.0f; f1 *= 2.0f; f2 *= 2.0f;
        }
        v[63] = 0.0f;
        uint32_t pk[32];
        #pragma unroll
        for (int i = 0; i < 32; i++) pk[i] = pack_h2(v[2 * i], v[2 * i + 1]);
        char* p = smraw + A_OFF + (uint32_t)tid * AROW;
        #pragma unroll
        for (int q = 0; q < 8; q++)
            *(uint4*)(p + q * 16) = ((uint4*)pk)[q];
    }
    // (gemm_run's first internal barrier orders enc writes vs fragment reads)

    float C[32][4];

    // ---------------- GEMM1: h1 = relu(enc @ w1 + b1), N=256, K=64 ----------------
    gemm_run<32>(C, 2, 256, g_w1T, 64, aP, bB, tid);
    {   // epilogue: bias+relu -> A plane (fp16)
        #pragma unroll
        for (int nt = 0; nt < 32; nt++) {
            int col = nt * 8 + 2 * (lane & 3);
            float2 bb = *(float2*)(smf + F_B1 + col);
            float v0 = fmaxf(C[nt][0] + bb.x, 0.f), v1 = fmaxf(C[nt][1] + bb.y, 0.f);
            float v2 = fmaxf(C[nt][2] + bb.x, 0.f), v3 = fmaxf(C[nt][3] + bb.y, 0.f);
            uint32_t o0 = (uint32_t)(16 * wid + (lane >> 2)) * AROW + (uint32_t)col * 2u;
            sts32(aP + o0, pack_h2(v0, v1));
            sts32(aP + o0 + 8 * AROW, pack_h2(v2, v3));
        }
    }
    // prefetch GEMM2 chunks 0,1
    cp_fill(bB,           g_w2T, 256, 256, 0,  tid); CP_COMMIT();
    cp_fill(bB + STAGE_B, g_w2T, 256, 256, 32, tid); CP_COMMIT();
    // dir-head rank-1 bias dc[2][128] (overlaps with prefetch latency)
    {
        int j = tid & 127, rr = tid >> 7;
        float acc = bdirg[j];
        #pragma unroll
        for (int dd = 0; dd < 27; dd++)
            acc = fmaf(smf[F_EDIR + rr * 32 + dd], wdirg[(256 + dd) * 128 + j], acc);
        smf[F_DC + rr * 128 + j] = acc;
    }

    // ---------------- GEMM2: h2 = relu(h1 @ w2 + b2), N=256, K=256 ----------------
    gemm_run<32>(C, 8, 256, g_w2T, 256, aP, bB, tid);
    {   // epilogue: bias+relu, fused sigma head, fp16 -> A plane
        float sl = 0.f, sh = 0.f;
        #pragma unroll
        for (int nt = 0; nt < 32; nt++) {
            int col = nt * 8 + 2 * (lane & 3);
            float2 bb = *(float2*)(smf + F_B2 + col);
            float2 ws = *(float2*)(smf + F_WSIG + col);
            float v0 = fmaxf(C[nt][0] + bb.x, 0.f), v1 = fmaxf(C[nt][1] + bb.y, 0.f);
            float v2 = fmaxf(C[nt][2] + bb.x, 0.f), v3 = fmaxf(C[nt][3] + bb.y, 0.f);
            sl = fmaf(v0, ws.x, fmaf(v1, ws.y, sl));
            sh = fmaf(v2, ws.x, fmaf(v3, ws.y, sh));
            uint32_t o0 = (uint32_t)(16 * wid + (lane >> 2)) * AROW + (uint32_t)col * 2u;
            sts32(aP + o0, pack_h2(v0, v1));
            sts32(aP + o0 + 8 * AROW, pack_h2(v2, v3));
        }
        sl = qred(sl); sh = qred(sh);
        if ((lane & 3) == 0) {
            float bs0 = bsigg[0];
            smf[F_SIG + 16 * wid + (lane >> 2)]     = sl + bs0;
            smf[F_SIG + 16 * wid + (lane >> 2) + 8] = sh + bs0;
        }
    }
    // prefetch GEMM3 chunks 0,1
    cp_fill(bB,           g_wdT, 128, 256, 0,  tid); CP_COMMIT();
    cp_fill(bB + STAGE_B, g_wdT, 128, 256, 32, tid); CP_COMMIT();

    // ---------------- GEMM3: hd = relu(h2 @ w_dir[0:256] + dc), N=128, K=256 --------
    gemm_run<16>(C, 8, 128, g_wdT, 256, aP, bB, tid);
    {   // epilogue: fused rgb head straight from fragments
        int row = 16 * wid + (lane >> 2);
        int ray = row >> 6;
        const float* dcp = smf + F_DC + ray * 128;
        float r0 = 0.f, g0 = 0.f, b0 = 0.f, r1 = 0.f, g1 = 0.f, b1v = 0.f;
        #pragma unroll
        for (int nt = 0; nt < 16; nt++) {
            int col = nt * 8 + 2 * (lane & 3);
            float d0 = dcp[col], d1 = dcp[col + 1];
            float h0 = fmaxf(C[nt][0] + d0, 0.f), h1 = fmaxf(C[nt][1] + d1, 0.f);
            float h2 = fmaxf(C[nt][2] + d0, 0.f), h3 = fmaxf(C[nt][3] + d1, 0.f);
            const float* w0 = smf + F_WRGB + col * 3;
            const float* w1v = w0 + 3;
            r0  = fmaf(h0, w0[0], fmaf(h1, w1v[0], r0));
            g0  = fmaf(h0, w0[1], fmaf(h1, w1v[1], g0));
            b0  = fmaf(h0, w0[2], fmaf(h1, w1v[2], b0));
            r1  = fmaf(h2, w0[0], fmaf(h3, w1v[0], r1));
            g1  = fmaf(h2, w0[1], fmaf(h3, w1v[1], g1));
            b1v = fmaf(h2, w0[2], fmaf(h3, w1v[2], b1v));
        }
        r0 = qred(r0); g0 = qred(g0); b0 = qred(b0);
        r1 = qred(r1); g1 = qred(g1); b1v = qred(b1v);
        if ((lane & 3) == 0) {
            float br = brgbg[0], bg = brgbg[1], bbv = brgbg[2];
            smf[F_RGB + row * 3 + 0] = 1.0f / (1.0f + expf(-(r0 + br)));
            smf[F_RGB + row * 3 + 1] = 1.0f / (1.0f + expf(-(g0 + bg)));
            smf[F_RGB + row * 3 + 2] = 1.0f / (1.0f + expf(-(b0 + bbv)));
            smf[F_RGB + (row + 8) * 3 + 0] = 1.0f / (1.0f + expf(-(r1 + br)));
            smf[F_RGB + (row + 8) * 3 + 1] = 1.0f / (1.0f + expf(-(g1 + bg)));
            smf[F_RGB + (row + 8) * 3 + 2] = 1.0f / (1.0f + expf(-(b1v + bbv)));
        }
    }
    __syncthreads();

    // ---------------- compositing (2 rays; exact sigma at the DINF sample) ----------
    if (tid < 2) {
        int ray = ray0 + tid;
        float nrm = smf[F_RAY + tid * 12 + 9];
        float sig_last = g_sig_last[ray];
        float T = 1.0f, r = 0.0f, g = 0.0f, b = 0.0f;
        #pragma unroll 1
        for (int s = 0; s < NSAMP; s++) {
            int m = tid * 64 + s;
            float sg = (s == 63) ? sig_last : smf[F_SIG + m];
            sg = fmaxf(sg, 0.0f);
            float a = 1.0f - expf(-sg * g_dists[s] * nrm);
            float w = a * T;
            r = fmaf(w, smf[F_RGB + m * 3 + 0], r);
            g = fmaf(w, smf[F_RGB + m * 3 + 1], g);
            b = fmaf(w, smf[F_RGB + m * 3 + 2], b);
            T *= (1.0f - a);
        }
        out[ray * 3 + 0] = r;
        out[ray * 3 + 1] = g;
        out[ray * 3 + 2] = b;
    }
}

extern "C" void kernel_launch(void* const* d_in, const int* in_sizes, int n_in,
                              void* d_out, int out_size) {
    const float* c2w    = (const float*)d_in[0];
    const float* t_rand = (const float*)d_in[1];
    const float* w1     = (const float*)d_in[2];
    const float* b1     = (const float*)d_in[3];
    const float* w2     = (const float*)d_in[4];
    const float* b2     = (const float*)d_in[5];
    const float* w_sig  = (const float*)d_in[6];
    const float* b_sig  = (const float*)d_in[7];
    const float* w_dir  = (const float*)d_in[8];
    const float* b_dir  = (const float*)d_in[9];
    const float* w_rgb  = (const float*)d_in[10];
    const float* b_rgb  = (const float*)d_in[11];
    float* out = (float*)d_out;

    cudaFuncSetAttribute(nerf_hmma16, cudaFuncAttributeMaxDynamicSharedMemorySize, SMEM_BYTES);

    precompute_kernel<<<1, NSAMP>>>(t_rand);
    prep_weights<<<448, 256>>>(w1, w2, w_dir);
    sigma_exact<<<625, 256>>>(c2w, w1, b1, w2, b2, w_sig, b_sig);
    nerf_hmma16<<<NBLOCKS, 256, SMEM_BYTES>>>(c2w, b1, b2, w_sig, b_sig,
                                              w_dir, b_dir, w_rgb, b_rgb, out);
}

// round 9
// speedup vs baseline: 5.3999x; 1.2743x over previous
#include <cuda_runtime.h>
#include <cuda_fp16.h>
#include <stdint.h>
#include <math.h>

#define NSAMP 64
#define NBLOCKS 5000           // 2 rays per block, M = 128 sample-rows
#define FXc 86.6f
#define NEAR_ 2.0f
#define FAR_ 6.0f
#define DINF 1e10f

// ---------------- global scratch (weights as fp16, [N][K]) ----------------
__device__ float g_z[NSAMP];
__device__ float g_dists[NSAMP];
__device__ float g_sig_last[10000];
__device__ __align__(16) __half g_w1T[256 * 64];
__device__ __align__(16) __half g_w2T[256 * 256];
__device__ __align__(16) __half g_wdT[128 * 256];

// ---------------- smem layout (bytes) ----------------
// [0, 11648)        misc floats
// [11648, 79232)    A plane: 128 rows x 264 fp16 (row stride 528 B)
// [79232, 189824)   B stages: 3 x 36864 B (256 rows x 72 fp16, 144 B stride)
#define A_OFF     11648u
#define B_OFF     79232u
#define STAGE_B   36864u
#define BROW      144u
#define AROW      528u
#define SMEM_BYTES 189824

// misc float offsets
#define F_RAY   0      // [2][12]: o(3) d(3) v(3) norm
#define F_B1    32
#define F_B2    288
#define F_WSIG  544
#define F_WRGB  800    // 384
#define F_EDIR  1184   // [2][32]
#define F_DC    1248   // [2][128]
#define F_SIGP  1504   // [2][128] sigma partials; later alpha in [0..127]
#define F_RGB   1760   // [128][3] final rgb
#define F_RGBP  2144   // [2][384] rgb partials

// ---------------- asm helpers ----------------
__device__ __forceinline__ uint32_t smem_u32(const void* p) {
    uint32_t a;
    asm("{ .reg .u64 t; cvta.to.shared.u64 t, %1; cvt.u32.u64 %0, t; }" : "=r"(a) : "l"(p));
    return a;
}
__device__ __forceinline__ uint32_t lds32(uint32_t a) {
    uint32_t v; asm volatile("ld.shared.b32 %0, [%1];" : "=r"(v) : "r"(a)); return v;
}
__device__ __forceinline__ void sts32(uint32_t a, uint32_t v) {
    asm volatile("st.shared.b32 [%0], %1;" :: "r"(a), "r"(v));
}
__device__ __forceinline__ void mma_f16(float* c, const uint32_t* a, uint32_t b0, uint32_t b1) {
    asm volatile(
        "mma.sync.aligned.m16n8k16.row.col.f32.f16.f16.f32 "
        "{%0,%1,%2,%3}, {%4,%5,%6,%7}, {%8,%9}, {%0,%1,%2,%3};"
        : "+f"(c[0]), "+f"(c[1]), "+f"(c[2]), "+f"(c[3])
        : "r"(a[0]), "r"(a[1]), "r"(a[2]), "r"(a[3]), "r"(b0), "r"(b1));
}
__device__ __forceinline__ void cpa16(uint32_t d, const void* s) {
    asm volatile("cp.async.ca.shared.global [%0], [%1], 16;" :: "r"(d), "l"(s));
}
#define CP_COMMIT() asm volatile("cp.async.commit_group;" ::: "memory")
#define CP_WAIT1()  asm volatile("cp.async.wait_group 1;" ::: "memory")

__device__ __forceinline__ uint32_t pack_h2(float a, float b) {
    __half2 h = __floats2half2_rn(a, b);
    return *reinterpret_cast<uint32_t*>(&h);
}
__device__ __forceinline__ float qred(float v) {
    v += __shfl_xor_sync(0xffffffffu, v, 1);
    v += __shfl_xor_sync(0xffffffffu, v, 2);
    return v;
}

// schedule: 9 items = G1 x1, G2 x4, G3 x4 (K=64 chunks)
__device__ __forceinline__ void fill_item(int t, uint32_t bB, int tid) {
    if (t >= 9) return;
    const __half* src; int nrows, kst, kb;
    if (t == 0)      { src = g_w1T; nrows = 256; kst = 64;  kb = 0; }
    else if (t < 5)  { src = g_w2T; nrows = 256; kst = 256; kb = (t - 1) * 64; }
    else             { src = g_wdT; nrows = 128; kst = 256; kb = (t - 5) * 64; }
    uint32_t dst = bB + (uint32_t)(t % 3) * STAGE_B;
    for (int i = tid; i < nrows * 8; i += 512) {
        int n = i >> 3, seg = i & 7;
        cpa16(dst + (uint32_t)n * BROW + (uint32_t)seg * 16u,
              src + n * kst + kb + seg * 8);
    }
}

// GEMM: M=128 (8 M-warp-groups x 16 rows), 2 N-warp-groups, K=64 per chunk.
// 3-stage ring, ONE barrier per chunk (fill(t+2) targets stage (t-1)%3 whose
// readers all passed this chunk's barrier).
template<int NT>
__device__ __forceinline__ void gemm_run(float (*C)[4], int nchunks,
                                         uint32_t aP, uint32_t bB, uint32_t nbase,
                                         int tid, int lane, int r0, int& t) {
    const uint32_t arow = (uint32_t)r0 * AROW + (uint32_t)(lane & 3) * 4u;
    const uint32_t brow = nbase + (uint32_t)(lane >> 2) * BROW + (uint32_t)(lane & 3) * 4u;
    #pragma unroll
    for (int i = 0; i < NT; i++) { C[i][0] = 0.f; C[i][1] = 0.f; C[i][2] = 0.f; C[i][3] = 0.f; }
    #pragma unroll 1
    for (int ch = 0; ch < nchunks; ch++) {
        CP_WAIT1();
        __syncthreads();
        uint32_t bs = bB + (uint32_t)(t % 3) * STAGE_B;
        #pragma unroll
        for (int k16 = 0; k16 < 4; k16++) {
            uint32_t kb = (uint32_t)(ch * 128 + k16 * 32);
            uint32_t ah = aP + arow + kb;
            uint32_t a[4];
            a[0] = lds32(ah);        a[1] = lds32(ah + 8 * AROW);
            a[2] = lds32(ah + 16);   a[3] = lds32(ah + 8 * AROW + 16);
            uint32_t bk = bs + brow + (uint32_t)k16 * 32u;
            #pragma unroll
            for (int nt = 0; nt < NT; nt++) {
                uint32_t ba = bk + (uint32_t)nt * (8u * BROW);
                mma_f16(C[nt], a, lds32(ba), lds32(ba + 16));
            }
        }
        fill_item(t + 2, bB, tid);
        CP_COMMIT();
        t++;
    }
}

// ---------------- aux kernels ----------------
__global__ void precompute_kernel(const float* __restrict__ t_rand) {
    __shared__ float zsh[NSAMP];
    int i = threadIdx.x;
    float t   = (float)i / 63.0f;
    float z0  = NEAR_ * (1.0f - t) + FAR_ * t;
    float tn  = (float)(i + 1) / 63.0f;
    float z0n = NEAR_ * (1.0f - tn) + FAR_ * tn;
    float tp  = (float)(i - 1) / 63.0f;
    float z0p = NEAR_ * (1.0f - tp) + FAR_ * tp;
    float upper = (i < NSAMP - 1) ? 0.5f * (z0 + z0n) : z0;
    float lower = (i > 0) ? 0.5f * (z0p + z0) : z0;
    float z = lower + (upper - lower) * t_rand[i];
    zsh[i] = z;
    g_z[i] = z;
    __syncthreads();
    g_dists[i] = (i < NSAMP - 1) ? (zsh[i + 1] - zsh[i]) : DINF;
}

__global__ void prep_weights(const float* __restrict__ w1,
                             const float* __restrict__ w2,
                             const float* __restrict__ wd) {
    int idx = blockIdx.x * 256 + threadIdx.x;
    if (idx < 16384) {
        int n = idx >> 6, k = idx & 63;
        g_w1T[idx] = __float2half((k < 63) ? w1[k * 256 + n] : 0.0f);
    } else if (idx < 16384 + 65536) {
        int t = idx - 16384; int n = t >> 8, k = t & 255;
        g_w2T[t] = __float2half(w2[k * 256 + n]);
    } else if (idx < 16384 + 65536 + 32768) {
        int t = idx - 16384 - 65536; int n = t >> 8, k = t & 255;
        g_wdT[t] = __float2half(wd[k * 128 + n]);
    }
}

// exact fp32 sigma for the LAST sample of each ray (alpha there is a step fn of sign(sigma))
__global__ void __launch_bounds__(256) sigma_exact(
    const float* __restrict__ c2w,
    const float* __restrict__ w1g, const float* __restrict__ b1g,
    const float* __restrict__ w2g, const float* __restrict__ b2g,
    const float* __restrict__ wsigg, const float* __restrict__ bsigg)
{
    __shared__ float enc[16][64];
    __shared__ float h1s[16][260];
    __shared__ float red[16][8];
    int tid = threadIdx.x;
    int r = tid >> 4, sub = tid & 15;
    {
        int ray = blockIdx.x * 16 + r;
        int cx = ray % 100, rw = ray / 100;
        float dx = ((float)cx - 50.0f) / FXc;
        float dy = -(((float)rw - 50.0f) / FXc);
        float d0 = dx * c2w[0] + dy * c2w[1] - c2w[2];
        float d1 = dx * c2w[4] + dy * c2w[5] - c2w[6];
        float d2 = dx * c2w[8] + dy * c2w[9] - c2w[10];
        float z = g_z[63];
        float pt[3];
        pt[0] = fmaf(d0, z, c2w[3]);
        pt[1] = fmaf(d1, z, c2w[7]);
        pt[2] = fmaf(d2, z, c2w[11]);
        #pragma unroll
        for (int q = 0; q < 4; q++) {
            int dd = sub * 4 + q;
            float val = 0.f;
            if (dd < 3) val = pt[dd];
            else if (dd < 63) {
                int u = dd - 3, l = u / 6, r6 = u % 6, cc = r6 % 3;
                float x = pt[cc] * (float)(1 << l);
                val = (r6 < 3) ? sinf(x) : cosf(x);
            }
            enc[r][dd] = val;
        }
    }
    __syncthreads();
    float acc[16];
    {
        float b = b1g[tid];
        #pragma unroll
        for (int i = 0; i < 16; i++) acc[i] = b;
        #pragma unroll 1
        for (int k = 0; k < 63; k++) {
            float w = w1g[k * 256 + tid];
            #pragma unroll
            for (int i = 0; i < 16; i++) acc[i] = fmaf(enc[i][k], w, acc[i]);
        }
        #pragma unroll
        for (int i = 0; i < 16; i++) h1s[i][tid] = fmaxf(acc[i], 0.f);
    }
    __syncthreads();
    {
        float b = b2g[tid];
        #pragma unroll
        for (int i = 0; i < 16; i++) acc[i] = b;
        #pragma unroll 1
        for (int k = 0; k < 256; k++) {
            float w = w2g[k * 256 + tid];
            #pragma unroll
            for (int i = 0; i < 16; i++) acc[i] = fmaf(h1s[i][k], w, acc[i]);
        }
    }
    {
        float ws = wsigg[tid];
        #pragma unroll
        for (int i = 0; i < 16; i++) {
            float v = fmaxf(acc[i], 0.f) * ws;
            v += __shfl_xor_sync(0xffffffffu, v, 16);
            v += __shfl_xor_sync(0xffffffffu, v, 8);
            v += __shfl_xor_sync(0xffffffffu, v, 4);
            v += __shfl_xor_sync(0xffffffffu, v, 2);
            v += __shfl_xor_sync(0xffffffffu, v, 1);
            if ((tid & 31) == 0) red[i][tid >> 5] = v;
        }
        __syncthreads();
        if (tid < 16) {
            float s = bsigg[0];
            #pragma unroll
            for (int w = 0; w < 8; w++) s += red[tid][w];
            g_sig_last[blockIdx.x * 16 + tid] = s;
        }
    }
}

// ---------------- main fused kernel (512 threads) ----------------
__global__ void __launch_bounds__(512, 1) nerf_v2(
    const float* __restrict__ c2w,
    const float* __restrict__ b1g,  const float* __restrict__ b2g,
    const float* __restrict__ wsigg,const float* __restrict__ bsigg,
    const float* __restrict__ wdirg,const float* __restrict__ bdirg,
    const float* __restrict__ wrgbg,const float* __restrict__ brgbg,
    float* __restrict__ out)
{
    extern __shared__ char smraw[];
    float* smf = (float*)smraw;
    const uint32_t base = smem_u32(smraw);
    const uint32_t aP = base + A_OFF, bB = base + B_OFF;
    const int tid = threadIdx.x, lane = tid & 31, wid = tid >> 5;
    const int wn = wid & 1, wm = wid >> 1;
    const int r0 = wm * 16 + (lane >> 2);
    const int ray0 = blockIdx.x * 2;
    int t = 0;

    // prefetch first two chunk items
    fill_item(0, bB, tid); CP_COMMIT();
    fill_item(1, bB, tid); CP_COMMIT();

    // stage small tensors
    if (tid < 256) {
        smf[F_B1 + tid]   = b1g[tid];
        smf[F_B2 + tid]   = b2g[tid];
        smf[F_WSIG + tid] = wsigg[tid];
    }
    if (tid < 384) smf[F_WRGB + tid] = wrgbg[tid];
    if (tid < 2) {
        int ray = ray0 + tid;
        int c = ray % 100, rw = ray / 100;
        float dx = ((float)c - 50.0f) / FXc;
        float dy = -(((float)rw - 50.0f) / FXc);
        float d0 = dx * c2w[0] + dy * c2w[1] - c2w[2];
        float d1 = dx * c2w[4] + dy * c2w[5] - c2w[6];
        float d2 = dx * c2w[8] + dy * c2w[9] - c2w[10];
        float nrm = sqrtf(d0 * d0 + d1 * d1 + d2 * d2);
        float* R = smf + F_RAY + tid * 12;
        R[0] = c2w[3]; R[1] = c2w[7]; R[2] = c2w[11];
        R[3] = d0; R[4] = d1; R[5] = d2;
        R[6] = d0 / nrm; R[7] = d1 / nrm; R[8] = d2 / nrm;
        R[9] = nrm;
    }
    __syncthreads();

    // enc_dir (27 per ray) — precise (feeds fp32 dc path)
    if (tid < 54) {
        int rr = tid / 27, dd = tid - rr * 27;
        const float* vv = smf + F_RAY + rr * 12 + 6;
        float val;
        if (dd < 3) val = vv[dd];
        else {
            int u = dd - 3, l = u / 6, r6 = u % 6, cc = r6 % 3;
            float x = vv[cc] * (float)(1 << l);
            val = (r6 < 3) ? sinf(x) : cosf(x);
        }
        smf[F_EDIR + rr * 32 + dd] = val;
    }
    __syncthreads();

    // dir-head rank-1 bias dc[2][128] (fp32)
    if (tid < 256) {
        int j = tid & 127, rr = tid >> 7;
        float acc = bdirg[j];
        #pragma unroll
        for (int dd = 0; dd < 27; dd++)
            acc = fmaf(smf[F_EDIR + rr * 32 + dd], wdirg[(256 + dd) * 128 + j], acc);
        smf[F_DC + rr * 128 + j] = acc;
    }

    // posenc(pts) -> A plane fp16; fast sin/cos (error << fp16 rounding budget)
    if (tid < 128) {
        int rr = tid >> 6, s = tid & 63;
        float z = g_z[s];
        const float* R = smf + F_RAY + rr * 12;
        float v[64];
        float f0 = fmaf(R[3], z, R[0]);
        float f1 = fmaf(R[4], z, R[1]);
        float f2 = fmaf(R[5], z, R[2]);
        v[0] = f0; v[1] = f1; v[2] = f2;
        #pragma unroll
        for (int l = 0; l < 10; l++) {
            int b = 3 + l * 6;
            v[b]     = __sinf(f0); v[b + 1] = __sinf(f1); v[b + 2] = __sinf(f2);
            v[b + 3] = __cosf(f0); v[b + 4] = __cosf(f1); v[b + 5] = __cosf(f2);
            f0 *= 2.0f; f1 *= 2.0f; f2 *= 2.0f;
        }
        v[63] = 0.0f;
        uint32_t pk[32];
        #pragma unroll
        for (int i = 0; i < 32; i++) pk[i] = pack_h2(v[2 * i], v[2 * i + 1]);
        char* p = smraw + A_OFF + (uint32_t)tid * AROW;
        #pragma unroll
        for (int q = 0; q < 8; q++)
            *(uint4*)(p + q * 16) = ((uint4*)pk)[q];
    }
    // (gemm_run's first barrier orders A writes vs reads)

    float C[16][4];

    // ---------------- GEMM1: h1 = relu(enc @ w1 + b1), N=256, K=64 ----------------
    gemm_run<16>(C, 1, aP, bB, (uint32_t)wn * 128u * BROW, tid, lane, r0, t);
    __syncthreads();
    {   // ep1: bias+relu -> A plane (fp16)
        #pragma unroll
        for (int nt = 0; nt < 16; nt++) {
            int col = wn * 128 + nt * 8 + 2 * (lane & 3);
            float2 bb = *(float2*)(smf + F_B1 + col);
            float v0 = fmaxf(C[nt][0] + bb.x, 0.f), v1 = fmaxf(C[nt][1] + bb.y, 0.f);
            float v2 = fmaxf(C[nt][2] + bb.x, 0.f), v3 = fmaxf(C[nt][3] + bb.y, 0.f);
            uint32_t o0 = (uint32_t)r0 * AROW + (uint32_t)col * 2u;
            sts32(aP + o0, pack_h2(v0, v1));
            sts32(aP + o0 + 8 * AROW, pack_h2(v2, v3));
        }
    }

    // ---------------- GEMM2: h2 = relu(h1 @ w2 + b2), N=256, K=256 ----------------
    gemm_run<16>(C, 4, aP, bB, (uint32_t)wn * 128u * BROW, tid, lane, r0, t);
    __syncthreads();
    {   // ep2: bias+relu -> A plane; sigma partial per N-half
        float sl = 0.f, sh = 0.f;
        #pragma unroll
        for (int nt = 0; nt < 16; nt++) {
            int col = wn * 128 + nt * 8 + 2 * (lane & 3);
            float2 bb = *(float2*)(smf + F_B2 + col);
            float2 ws = *(float2*)(smf + F_WSIG + col);
            float v0 = fmaxf(C[nt][0] + bb.x, 0.f), v1 = fmaxf(C[nt][1] + bb.y, 0.f);
            float v2 = fmaxf(C[nt][2] + bb.x, 0.f), v3 = fmaxf(C[nt][3] + bb.y, 0.f);
            sl = fmaf(v0, ws.x, fmaf(v1, ws.y, sl));
            sh = fmaf(v2, ws.x, fmaf(v3, ws.y, sh));
            uint32_t o0 = (uint32_t)r0 * AROW + (uint32_t)col * 2u;
            sts32(aP + o0, pack_h2(v0, v1));
            sts32(aP + o0 + 8 * AROW, pack_h2(v2, v3));
        }
        sl = qred(sl); sh = qred(sh);
        if ((lane & 3) == 0) {
            smf[F_SIGP + wn * 128 + r0]     = sl;
            smf[F_SIGP + wn * 128 + r0 + 8] = sh;
        }
    }

    // ---------------- GEMM3: hd = relu(h2 @ w_dir_top + dc), N=128, K=256 ----------
    gemm_run<8>(C, 4, aP, bB, (uint32_t)wn * 64u * BROW, tid, lane, r0, t);
    __syncthreads();
    {   // ep3: rgb partial per N-half (relu+dc applied per-col in-warp)
        int ray = wm >> 2;
        const float* dcp = smf + F_DC + ray * 128;
        float r0a = 0.f, g0a = 0.f, b0a = 0.f, r1a = 0.f, g1a = 0.f, b1a = 0.f;
        #pragma unroll
        for (int nt = 0; nt < 8; nt++) {
            int col = wn * 64 + nt * 8 + 2 * (lane & 3);
            float d0 = dcp[col], d1 = dcp[col + 1];
            float h0 = fmaxf(C[nt][0] + d0, 0.f), h1 = fmaxf(C[nt][1] + d1, 0.f);
            float h2 = fmaxf(C[nt][2] + d0, 0.f), h3 = fmaxf(C[nt][3] + d1, 0.f);
            const float* w0 = smf + F_WRGB + col * 3;
            const float* w1v = w0 + 3;
            r0a = fmaf(h0, w0[0], fmaf(h1, w1v[0], r0a));
            g0a = fmaf(h0, w0[1], fmaf(h1, w1v[1], g0a));
            b0a = fmaf(h0, w0[2], fmaf(h1, w1v[2], b0a));
            r1a = fmaf(h2, w0[0], fmaf(h3, w1v[0], r1a));
            g1a = fmaf(h2, w0[1], fmaf(h3, w1v[1], g1a));
            b1a = fmaf(h2, w0[2], fmaf(h3, w1v[2], b1a));
        }
        r0a = qred(r0a); g0a = qred(g0a); b0a = qred(b0a);
        r1a = qred(r1a); g1a = qred(g1a); b1a = qred(b1a);
        if ((lane & 3) == 0) {
            float* P = smf + F_RGBP + wn * 384;
            P[r0 * 3 + 0] = r0a; P[r0 * 3 + 1] = g0a; P[r0 * 3 + 2] = b0a;
            P[(r0 + 8) * 3 + 0] = r1a; P[(r0 + 8) * 3 + 1] = g1a; P[(r0 + 8) * 3 + 2] = b1a;
        }
    }
    __syncthreads();

    // final combine: sigmoid(rgb), alpha (exact sigma at the DINF sample)
    if (tid < 128) {
        int row = tid, rr = row >> 6, s = row & 63;
        float sg = smf[F_SIGP + row] + smf[F_SIGP + 128 + row] + bsigg[0];
        if (s == 63) sg = g_sig_last[ray0 + rr];
        float nrm = smf[F_RAY + rr * 12 + 9];
        smf[F_SIGP + row] = 1.0f - expf(-fmaxf(sg, 0.f) * g_dists[s] * nrm);
        #pragma unroll
        for (int c = 0; c < 3; c++) {
            float v = smf[F_RGBP + row * 3 + c] + smf[F_RGBP + 384 + row * 3 + c] + brgbg[c];
            smf[F_RGB + row * 3 + c] = 1.0f / (1.0f + expf(-v));
        }
    }
    __syncthreads();

    // compositing: cheap serial scan over precomputed alphas
    if (tid < 2) {
        int ray = ray0 + tid;
        float T = 1.0f, r = 0.0f, g = 0.0f, b = 0.0f;
        #pragma unroll 1
        for (int s = 0; s < NSAMP; s++) {
            int m = tid * 64 + s;
            float a = smf[F_SIGP + m];
            float w = a * T;
            r = fmaf(w, smf[F_RGB + m * 3 + 0], r);
            g = fmaf(w, smf[F_RGB + m * 3 + 1], g);
            b = fmaf(w, smf[F_RGB + m * 3 + 2], b);
            T *= (1.0f - a);
        }
        out[ray * 3 + 0] = r;
        out[ray * 3 + 1] = g;
        out[ray * 3 + 2] = b;
    }
}

extern "C" void kernel_launch(void* const* d_in, const int* in_sizes, int n_in,
                              void* d_out, int out_size) {
    const float* c2w    = (const float*)d_in[0];
    const float* t_rand = (const float*)d_in[1];
    const float* w1     = (const float*)d_in[2];
    const float* b1     = (const float*)d_in[3];
    const float* w2     = (const float*)d_in[4];
    const float* b2     = (const float*)d_in[5];
    const float* w_sig  = (const float*)d_in[6];
    const float* b_sig  = (const float*)d_in[7];
    const float* w_dir  = (const float*)d_in[8];
    const float* b_dir  = (const float*)d_in[9];
    const float* w_rgb  = (const float*)d_in[10];
    const float* b_rgb  = (const float*)d_in[11];
    float* out = (float*)d_out;

    cudaFuncSetAttribute(nerf_v2, cudaFuncAttributeMaxDynamicSharedMemorySize, SMEM_BYTES);

    precompute_kernel<<<1, NSAMP>>>(t_rand);
    prep_weights<<<448, 256>>>(w1, w2, w_dir);
    sigma_exact<<<625, 256>>>(c2w, w1, b1, w2, b2, w_sig, b_sig);
    nerf_v2<<<NBLOCKS, 512, SMEM_BYTES>>>(c2w, b1, b2, w_sig, b_sig,
                                          w_dir, b_dir, w_rgb, b_rgb, out);
}